// round 1
// baseline (speedup 1.0000x reference)
#include <cuda_runtime.h>

// Problem constants (fixed by the dataset)
#define NN_MAX 20000
#define EE_MAX 50000
#define H64 64

// ---------------- scratch (static device globals; no runtime allocation) ----
__device__ float g_h[EE_MAX * H64];            // edge MLP output, 12.8 MB
__device__ float g_w2r[65 * 64 * H64];         // permuted w2 + bias rows (max layer-1 size)
__device__ float g_agg[NN_MAX * H64];          // per-layer accumulator
__device__ float g_x1[NN_MAX * H64];           // layer-0 output

// ---------------- kernel 1: h = relu(ea @ w1 + b1) --------------------------
__global__ void edge_mlp_kernel(const float* __restrict__ ea,
                                const float* __restrict__ w1,
                                const float* __restrict__ b1,
                                int E)
{
    int idx = blockIdx.x * blockDim.x + threadIdx.x;
    if (idx >= E * H64) return;
    int e = idx >> 6, j = idx & 63;
    float a0 = __ldg(&ea[2 * e]);
    float a1 = __ldg(&ea[2 * e + 1]);
    float v = fmaf(a0, __ldg(&w1[j]), fmaf(a1, __ldg(&w1[H64 + j]), __ldg(&b1[j])));
    g_h[idx] = fmaxf(v, 0.0f);
}

// ---------------- kernel 2: permute w2 into (k,i)-major; append b2 rows -----
// g_w2r[(k*IN + i)*64 + o] = w2[k, i*64 + o];  g_w2r[(64*IN + i)*64 + o] = b2[i*64+o]
template<int IN_C>
__global__ void prep_w2r_kernel(const float* __restrict__ w2,
                                const float* __restrict__ b2)
{
    constexpr int TOT = 65 * IN_C * H64;
    int idx = blockIdx.x * blockDim.x + threadIdx.x;
    if (idx >= TOT) return;
    int kap = idx >> 6, o = idx & 63;
    float v;
    if (kap < 64 * IN_C) {
        int k = kap / IN_C, i = kap % IN_C;
        v = w2[k * (IN_C * H64) + i * H64 + o];
    } else {
        int i = kap - 64 * IN_C;
        v = b2[i * H64 + o];
    }
    g_w2r[idx] = v;
}

// ---------------- kernel 3: agg = x @ root + bias ---------------------------
template<int IN_C>
__global__ void root_init_kernel(const float* __restrict__ x,
                                 const float* __restrict__ root,
                                 const float* __restrict__ bias)
{
    __shared__ float xr[IN_C];
    int n = blockIdx.x, t = threadIdx.x;
    if (t < IN_C) xr[t] = x[n * IN_C + t];
    __syncthreads();
    float v = __ldg(&bias[t]);
    #pragma unroll
    for (int i = 0; i < IN_C; i++)
        v = fmaf(xr[i], __ldg(&root[i * H64 + t]), v);
    g_agg[n * H64 + t] = v;
}

// ---------------- kernel 4: fused msg GEMM + scatter-add --------------------
// C-tile: 64 edges x 64 outs per CTA (256 threads; 2 edges x 8 outs / thread).
// A row synthesized on the fly: A[e, k*IN+i] = h[e,k]*x[src,i]; bias tail A = x.
template<int IN_C>
__global__ void __launch_bounds__(256)
fused_msg_kernel(const float* __restrict__ x,
                 const int* __restrict__ ei,
                 int E)
{
    constexpr int TM = 64;
    constexpr int NCHUNK = (65 * IN_C) / 32;   // 65 (L0) or 130 (L1)
    __shared__ float h_s[TM][65];
    __shared__ float x_s[TM][IN_C + 1];
    __shared__ float B_s[32][64];
    __shared__ int   dst_s[TM];

    int tid = threadIdx.x;
    int e0  = blockIdx.x * TM;

    // load h tile (zero-fill OOB edges -> they contribute nothing)
    for (int q = tid; q < TM * 16; q += 256) {
        int e = q >> 4, c = q & 15;
        int ge = e0 + e;
        float4 v = make_float4(0.f, 0.f, 0.f, 0.f);
        if (ge < E) v = *(const float4*)(g_h + (size_t)ge * H64 + c * 4);
        h_s[e][c * 4 + 0] = v.x; h_s[e][c * 4 + 1] = v.y;
        h_s[e][c * 4 + 2] = v.z; h_s[e][c * 4 + 3] = v.w;
    }
    // gather x[src]
    constexpr int XV = IN_C / 4;
    for (int q = tid; q < TM * XV; q += 256) {
        int e = q / XV, c = q % XV;
        int ge = e0 + e;
        int s = (ge < E) ? ei[ge] : 0;
        float4 v = *(const float4*)(x + (size_t)s * IN_C + c * 4);
        x_s[e][c * 4 + 0] = v.x; x_s[e][c * 4 + 1] = v.y;
        x_s[e][c * 4 + 2] = v.z; x_s[e][c * 4 + 3] = v.w;
    }
    if (tid < TM) dst_s[tid] = (e0 + tid < E) ? ei[E + e0 + tid] : -1;

    int ty = tid >> 3, tx = tid & 7;
    int er0 = ty * 2, er1 = er0 + 1;
    float acc0[8] = {0.f, 0.f, 0.f, 0.f, 0.f, 0.f, 0.f, 0.f};
    float acc1[8] = {0.f, 0.f, 0.f, 0.f, 0.f, 0.f, 0.f, 0.f};

    for (int cch = 0; cch < NCHUNK; cch++) {
        __syncthreads();
        // stage 32 rows of w2r (2048 floats) into SMEM
        const float4* s4 = (const float4*)(g_w2r + (size_t)cch * 32 * 64);
        float4* d4 = (float4*)(&B_s[0][0]);
        d4[tid]       = s4[tid];
        d4[tid + 256] = s4[tid + 256];
        __syncthreads();

        int  kap0 = cch * 32;
        bool isB  = (kap0 >= 64 * IN_C);
        int  k    = kap0 / IN_C;        // constant within a 32-chunk (IN_C >= 32)
        int  i0   = kap0 % IN_C;        // works for bias tail too
        float hk0 = isB ? 1.0f : h_s[er0][k];
        float hk1 = isB ? 1.0f : h_s[er1][k];

        #pragma unroll 8
        for (int j = 0; j < 32; j++) {
            float a0 = hk0 * x_s[er0][i0 + j];
            float a1 = hk1 * x_s[er1][i0 + j];
            float4 b0 = *(const float4*)&B_s[j][tx * 8];
            float4 b1 = *(const float4*)&B_s[j][tx * 8 + 4];
            acc0[0] = fmaf(a0, b0.x, acc0[0]);
            acc0[1] = fmaf(a0, b0.y, acc0[1]);
            acc0[2] = fmaf(a0, b0.z, acc0[2]);
            acc0[3] = fmaf(a0, b0.w, acc0[3]);
            acc0[4] = fmaf(a0, b1.x, acc0[4]);
            acc0[5] = fmaf(a0, b1.y, acc0[5]);
            acc0[6] = fmaf(a0, b1.z, acc0[6]);
            acc0[7] = fmaf(a0, b1.w, acc0[7]);
            acc1[0] = fmaf(a1, b0.x, acc1[0]);
            acc1[1] = fmaf(a1, b0.y, acc1[1]);
            acc1[2] = fmaf(a1, b0.z, acc1[2]);
            acc1[3] = fmaf(a1, b0.w, acc1[3]);
            acc1[4] = fmaf(a1, b1.x, acc1[4]);
            acc1[5] = fmaf(a1, b1.y, acc1[5]);
            acc1[6] = fmaf(a1, b1.z, acc1[6]);
            acc1[7] = fmaf(a1, b1.w, acc1[7]);
        }
    }

    // scatter-add into agg[dst]
    int d0 = dst_s[er0], d1 = dst_s[er1];
    if (d0 >= 0) {
        float* p = g_agg + (size_t)d0 * H64 + tx * 8;
        #pragma unroll
        for (int u = 0; u < 8; u++) atomicAdd(p + u, acc0[u]);
    }
    if (d1 >= 0) {
        float* p = g_agg + (size_t)d1 * H64 + tx * 8;
        #pragma unroll
        for (int u = 0; u < 8; u++) atomicAdd(p + u, acc1[u]);
    }
}

// ---------------- kernel 5: out = relu(agg) ---------------------------------
__global__ void relu_out_kernel(float* __restrict__ out, int n)
{
    int i = blockIdx.x * blockDim.x + threadIdx.x;
    if (i < n) out[i] = fmaxf(g_agg[i], 0.0f);
}

// ---------------- launch -----------------------------------------------------
extern "C" void kernel_launch(void* const* d_in, const int* in_sizes, int n_in,
                              void* d_out, int out_size)
{
    const float* x      = (const float*)d_in[0];
    const int*   ei     = (const int*)  d_in[1];
    const float* ea     = (const float*)d_in[2];
    const float* w1_0   = (const float*)d_in[3];
    const float* b1_0   = (const float*)d_in[4];
    const float* w2_0   = (const float*)d_in[5];
    const float* b2_0   = (const float*)d_in[6];
    const float* root_0 = (const float*)d_in[7];
    const float* bias_0 = (const float*)d_in[8];
    const float* w1_1   = (const float*)d_in[9];
    const float* b1_1   = (const float*)d_in[10];
    const float* w2_1   = (const float*)d_in[11];
    const float* b2_1   = (const float*)d_in[12];
    const float* root_1 = (const float*)d_in[13];
    const float* bias_1 = (const float*)d_in[14];

    const int N = in_sizes[0] / 32;   // 20000
    const int E = in_sizes[1] / 2;    // 50000

    void* p = nullptr;
    cudaGetSymbolAddress(&p, g_x1);
    float* x1 = (float*)p;

    const int threads = 256;
    const int grid_h    = (E * H64 + threads - 1) / threads;
    const int grid_fuse = (E + 63) / 64;
    const int grid_relu = (N * H64 + threads - 1) / threads;

    // ---------------- layer 0 (IN=32) ----------------
    edge_mlp_kernel<<<grid_h, threads>>>(ea, w1_0, b1_0, E);
    prep_w2r_kernel<32><<<(65 * 32 * H64 + threads - 1) / threads, threads>>>(w2_0, b2_0);
    root_init_kernel<32><<<N, H64>>>(x, root_0, bias_0);
    fused_msg_kernel<32><<<grid_fuse, threads>>>(x, ei, E);
    relu_out_kernel<<<grid_relu, threads>>>(x1, N * H64);

    // ---------------- layer 1 (IN=64) ----------------
    edge_mlp_kernel<<<grid_h, threads>>>(ea, w1_1, b1_1, E);
    prep_w2r_kernel<64><<<(65 * 64 * H64 + threads - 1) / threads, threads>>>(w2_1, b2_1);
    root_init_kernel<64><<<N, H64>>>(x1, root_1, bias_1);
    fused_msg_kernel<64><<<grid_fuse, threads>>>(x1, ei, E);
    relu_out_kernel<<<grid_relu, threads>>>((float*)d_out, N * H64);
}

// round 2
// speedup vs baseline: 1.9123x; 1.9123x over previous
#include <cuda_runtime.h>

// Problem constants (fixed by the dataset)
#define NN_MAX 20000
#define EE_MAX 50000
#define H64 64

// ---------------- scratch (static device globals; no runtime allocation) ----
__device__ float g_ht[EE_MAX * H64 + 128];     // edge MLP output, TRANSPOSED [k][e] (+pad)
__device__ float g_w2r[65 * 64 * H64];         // permuted w2 + bias rows (max layer-1 size)
__device__ float g_agg[NN_MAX * H64];          // per-layer accumulator
__device__ float g_x1[NN_MAX * H64];           // layer-0 output

// ---------------- small PTX helpers -----------------------------------------
__device__ __forceinline__ void cp_async16(void* s, const void* g) {
    unsigned sa = (unsigned)__cvta_generic_to_shared(s);
    asm volatile("cp.async.cg.shared.global [%0], [%1], 16;\n" :: "r"(sa), "l"(g));
}
#define CP_COMMIT() asm volatile("cp.async.commit_group;\n" ::: "memory")
#define CP_WAIT1()  asm volatile("cp.async.wait_group 1;\n" ::: "memory")

__device__ __forceinline__ unsigned long long fma2(unsigned long long a,
                                                   unsigned long long b,
                                                   unsigned long long c) {
    unsigned long long d;
    asm("fma.rn.f32x2 %0, %1, %2, %3;" : "=l"(d) : "l"(a), "l"(b), "l"(c));
    return d;
}

// ---------------- kernel 1: h^T = relu(ea @ w1 + b1), stored [j][e] ---------
__global__ void edge_mlp_kernel(const float* __restrict__ ea,
                                const float* __restrict__ w1,
                                const float* __restrict__ b1,
                                int E)
{
    int e = blockIdx.x * blockDim.x + threadIdx.x;
    int j = blockIdx.y;
    if (e >= E) return;
    float a0 = __ldg(&ea[2 * e]);
    float a1 = __ldg(&ea[2 * e + 1]);
    float v = fmaf(a0, __ldg(&w1[j]), fmaf(a1, __ldg(&w1[H64 + j]), __ldg(&b1[j])));
    g_ht[(size_t)j * E + e] = fmaxf(v, 0.0f);
}

// ---------------- kernel 2: permute w2 into (k,i)-major; append b2 rows -----
// g_w2r[(k*IN + i)*64 + o] = w2[k, i*64 + o];  g_w2r[(64*IN + i)*64 + o] = b2[i*64+o]
template<int IN_C>
__global__ void prep_w2r_kernel(const float* __restrict__ w2,
                                const float* __restrict__ b2)
{
    constexpr int TOT = 65 * IN_C * H64;
    int idx = blockIdx.x * blockDim.x + threadIdx.x;
    if (idx >= TOT) return;
    int kap = idx >> 6, o = idx & 63;
    float v;
    if (kap < 64 * IN_C) {
        int k = kap / IN_C, i = kap % IN_C;
        v = w2[k * (IN_C * H64) + i * H64 + o];
    } else {
        int i = kap - 64 * IN_C;
        v = b2[i * H64 + o];
    }
    g_w2r[idx] = v;
}

// ---------------- kernel 3: agg = x @ root + bias ---------------------------
template<int IN_C>
__global__ void root_init_kernel(const float* __restrict__ x,
                                 const float* __restrict__ root,
                                 const float* __restrict__ bias)
{
    __shared__ float xr[IN_C];
    int n = blockIdx.x, t = threadIdx.x;
    if (t < IN_C) xr[t] = x[n * IN_C + t];
    __syncthreads();
    float v = __ldg(&bias[t]);
    #pragma unroll
    for (int i = 0; i < IN_C; i++)
        v = fmaf(xr[i], __ldg(&root[i * H64 + t]), v);
    g_agg[n * H64 + t] = v;
}

// ---------------- kernel 4: fused msg GEMM + scatter-add --------------------
// C-tile: 128 edges x 64 outs per CTA (256 threads; 4 edges x 8 outs / thread).
// A row synthesized on the fly: A[e, k*IN+i] = h[e,k]*x[src,i]; bias tail A = x.
// B (w2r) streamed via cp.async, 3-stage pipeline, ONE barrier per chunk.
template<int IN_C>
__global__ void __launch_bounds__(256)
fused_msg_kernel(const float* __restrict__ x,
                 const int* __restrict__ ei,
                 int E)
{
    constexpr int TM = 128;
    constexpr int NCHUNK = (65 * IN_C) / 32;   // 65 (L0) or 130 (L1)

    __shared__ float x_s[TM][IN_C + 1];
    __shared__ float B_s[3][32][64];
    __shared__ float h_s[3][TM];
    __shared__ int   dst_s[TM];

    int tid = threadIdx.x;
    int e0  = blockIdx.x * TM;

    // ---- gather x[src] tile (src=0 for OOB edges; results discarded) ----
    constexpr int XV = IN_C / 4;
    for (int q = tid; q < TM * XV; q += 256) {
        int e = q / XV, c = q % XV;
        int ge = e0 + e;
        int s = (ge < E) ? ei[ge] : 0;
        float4 v = *(const float4*)(x + (size_t)s * IN_C + c * 4);
        x_s[e][c * 4 + 0] = v.x; x_s[e][c * 4 + 1] = v.y;
        x_s[e][c * 4 + 2] = v.z; x_s[e][c * 4 + 3] = v.w;
    }
    if (tid < TM) dst_s[tid] = (e0 + tid < E) ? ei[E + e0 + tid] : -1;

    // ---- prefetch helper (B chunk + h column) ----
    auto prefetch = [&](int c, int slot) {
        if (c < NCHUNK) {
            const float* src = g_w2r + (size_t)c * 2048;
            float* dstB = &B_s[slot][0][0];
            cp_async16(dstB + tid * 4,        src + tid * 4);
            cp_async16(dstB + 1024 + tid * 4, src + 1024 + tid * 4);
            int kb = c * 32;
            if (kb < 64 * IN_C && tid < 32) {
                int k = kb / IN_C;
                cp_async16(&h_s[slot][tid * 4], g_ht + (size_t)k * E + e0 + tid * 4);
            }
        }
        CP_COMMIT();   // always commit (possibly empty group) to keep counts uniform
    };

    prefetch(0, 0);
    prefetch(1, 1);

    int ty = tid >> 3, tx = tid & 7;
    int er0 = ty * 4;
    int tx8 = tx * 8;
    unsigned long long acc[4][4];
    #pragma unroll
    for (int u = 0; u < 4; u++)
        #pragma unroll
        for (int q = 0; q < 4; q++) acc[u][q] = 0ull;

    for (int c = 0; c < NCHUNK; c++) {
        int slot = c % 3;
        CP_WAIT1();          // chunk c's group complete (this thread)
        __syncthreads();     // all threads' copies visible; all done computing c-1
        prefetch(c + 2, (c + 2) % 3);   // target slot last read at chunk c-1 -> safe

        int  kb  = c * 32;
        bool isB = (kb >= 64 * IN_C);
        int  i0  = kb % IN_C;
        float hk[4];
        #pragma unroll
        for (int u = 0; u < 4; u++)
            hk[u] = isB ? 1.0f : h_s[slot][er0 + u];

        #pragma unroll 4
        for (int j = 0; j < 32; j++) {
            ulonglong2 b01 = *(const ulonglong2*)&B_s[slot][j][tx8];
            ulonglong2 b23 = *(const ulonglong2*)&B_s[slot][j][tx8 + 4];
            #pragma unroll
            for (int u = 0; u < 4; u++) {
                float a = hk[u] * x_s[er0 + u][i0 + j];
                unsigned long long aa;
                asm("mov.b64 %0, {%1, %1};" : "=l"(aa) : "r"(__float_as_uint(a)));
                acc[u][0] = fma2(aa, b01.x, acc[u][0]);
                acc[u][1] = fma2(aa, b01.y, acc[u][1]);
                acc[u][2] = fma2(aa, b23.x, acc[u][2]);
                acc[u][3] = fma2(aa, b23.y, acc[u][3]);
            }
        }
    }

    // ---- scatter-add into agg[dst] ----
    #pragma unroll
    for (int u = 0; u < 4; u++) {
        int d = dst_s[er0 + u];
        if (d >= 0) {
            float* p = g_agg + (size_t)d * H64 + tx8;
            #pragma unroll
            for (int q = 0; q < 4; q++) {
                unsigned lo, hi;
                asm("mov.b64 {%0, %1}, %2;" : "=r"(lo), "=r"(hi) : "l"(acc[u][q]));
                atomicAdd(p + 2 * q,     __uint_as_float(lo));
                atomicAdd(p + 2 * q + 1, __uint_as_float(hi));
            }
        }
    }
}

// ---------------- kernel 5: out = relu(agg) ---------------------------------
__global__ void relu_out_kernel(float* __restrict__ out, int n)
{
    int i = blockIdx.x * blockDim.x + threadIdx.x;
    if (i < n) out[i] = fmaxf(g_agg[i], 0.0f);
}

// ---------------- launch -----------------------------------------------------
extern "C" void kernel_launch(void* const* d_in, const int* in_sizes, int n_in,
                              void* d_out, int out_size)
{
    const float* x      = (const float*)d_in[0];
    const int*   ei     = (const int*)  d_in[1];
    const float* ea     = (const float*)d_in[2];
    const float* w1_0   = (const float*)d_in[3];
    const float* b1_0   = (const float*)d_in[4];
    const float* w2_0   = (const float*)d_in[5];
    const float* b2_0   = (const float*)d_in[6];
    const float* root_0 = (const float*)d_in[7];
    const float* bias_0 = (const float*)d_in[8];
    const float* w1_1   = (const float*)d_in[9];
    const float* b1_1   = (const float*)d_in[10];
    const float* w2_1   = (const float*)d_in[11];
    const float* b2_1   = (const float*)d_in[12];
    const float* root_1 = (const float*)d_in[13];
    const float* bias_1 = (const float*)d_in[14];

    const int N = in_sizes[0] / 32;   // 20000
    const int E = in_sizes[1] / 2;    // 50000

    void* p = nullptr;
    cudaGetSymbolAddress(&p, g_x1);
    float* x1 = (float*)p;

    const int threads = 256;
    dim3 grid_h((E + threads - 1) / threads, H64);
    const int grid_fuse = (E + 127) / 128;
    const int grid_relu = (N * H64 + threads - 1) / threads;

    // ---------------- layer 0 (IN=32) ----------------
    edge_mlp_kernel<<<grid_h, threads>>>(ea, w1_0, b1_0, E);
    prep_w2r_kernel<32><<<(65 * 32 * H64 + threads - 1) / threads, threads>>>(w2_0, b2_0);
    root_init_kernel<32><<<N, H64>>>(x, root_0, bias_0);
    fused_msg_kernel<32><<<grid_fuse, threads>>>(x, ei, E);
    relu_out_kernel<<<grid_relu, threads>>>(x1, N * H64);

    // ---------------- layer 1 (IN=64) ----------------
    edge_mlp_kernel<<<grid_h, threads>>>(ea, w1_1, b1_1, E);
    prep_w2r_kernel<64><<<(65 * 64 * H64 + threads - 1) / threads, threads>>>(w2_1, b2_1);
    root_init_kernel<64><<<N, H64>>>(x1, root_1, bias_1);
    fused_msg_kernel<64><<<grid_fuse, threads>>>(x1, ei, E);
    relu_out_kernel<<<grid_relu, threads>>>((float*)d_out, N * H64);
}

// round 4
// speedup vs baseline: 8.5552x; 4.4737x over previous
#include <cuda_runtime.h>
#include <cstdint>

#define H64 64
#define EE_MAX 50000
#define NN_MAX 20000

// ---------------- scratch (static device globals) ---------------------------
__device__ float    g_ht[EE_MAX * H64 + 256];   // edge MLP out, transposed [k][e]
__device__ uint32_t g_w2b[130 * 2176];          // packed tf32 B chunks (pair layout)
__device__ float    g_agg[NN_MAX * H64];
__device__ float    g_x1[NN_MAX * H64];

// ---------------- PTX helpers ------------------------------------------------
__device__ __forceinline__ uint32_t smem_u32(const void* p) {
    return (uint32_t)__cvta_generic_to_shared(p);
}
__device__ __forceinline__ uint32_t tf32r(float f) {
    uint32_t u; asm("cvt.rna.tf32.f32 %0, %1;" : "=r"(u) : "f"(f)); return u;
}
__device__ __forceinline__ void cp_async16(uint32_t s, const void* g) {
    asm volatile("cp.async.cg.shared.global [%0], [%1], 16;" :: "r"(s), "l"(g));
}
#define CP_COMMIT() asm volatile("cp.async.commit_group;" ::: "memory")
#define CP_WAIT1()  asm volatile("cp.async.wait_group 1;" ::: "memory")

__device__ __forceinline__ void mma_tf32(float* d, uint32_t a0, uint32_t a1,
                                         uint32_t a2, uint32_t a3,
                                         uint32_t b0, uint32_t b1) {
    asm volatile(
        "mma.sync.aligned.m16n8k8.row.col.f32.tf32.tf32.f32 "
        "{%0,%1,%2,%3}, {%4,%5,%6,%7}, {%8,%9}, {%0,%1,%2,%3};"
        : "+f"(d[0]), "+f"(d[1]), "+f"(d[2]), "+f"(d[3])
        : "r"(a0), "r"(a1), "r"(a2), "r"(a3), "r"(b0), "r"(b1));
}

// ---------------- kernel 1: h^T = relu(ea @ w1 + b1), stored [j][e] ---------
__global__ void edge_mlp_kernel(const float* __restrict__ ea,
                                const float* __restrict__ w1,
                                const float* __restrict__ b1, int E)
{
    int e = blockIdx.x * blockDim.x + threadIdx.x;
    int j = blockIdx.y;
    if (e >= E) return;
    float a0 = __ldg(&ea[2 * e]);
    float a1 = __ldg(&ea[2 * e + 1]);
    float v = fmaf(a0, __ldg(&w1[j]), fmaf(a1, __ldg(&w1[H64 + j]), __ldg(&b1[j])));
    g_ht[(size_t)j * E + e] = fmaxf(v, 0.0f);
}

// ---------------- kernel 2: pack tf32 B chunks (mma b-fragment pair layout) --
// chunk c: 16 rows (row = s*4 + t; s=k-step 0..3, t=k%4), 64 cols n, pair p:
//   value(k_local = s*8 + t + 4*p), kap = c*32 + k_local
// word offset within chunk: row*136 + n*2 + p   (row stride 68 pairs, pad 4)
template<int IN_C>
__global__ void prep_w2b_kernel(const float* __restrict__ w2,
                                const float* __restrict__ b2)
{
    constexpr int NCHUNK = (65 * IN_C) / 32;
    int idx = blockIdx.x * blockDim.x + threadIdx.x;
    if (idx >= NCHUNK * 2048) return;
    int c = idx >> 11, rem = idx & 2047;
    int n = rem & 63;
    int rowp = rem >> 6;             // 0..31
    int row = rowp >> 1, p = rowp & 1;
    int s = row >> 2, t = row & 3;
    int kap = c * 32 + s * 8 + t + 4 * p;
    float v;
    if (kap < 64 * IN_C) {
        int kk = kap / IN_C, i = kap % IN_C;
        v = w2[kk * (IN_C * H64) + i * H64 + n];
    } else {
        int i = kap - 64 * IN_C;
        v = b2[i * H64 + n];
    }
    g_w2b[c * 2176 + row * 136 + n * 2 + p] = tf32r(v);
}

// ---------------- kernel 3: agg = x @ root + bias ---------------------------
template<int IN_C>
__global__ void root_init_kernel(const float* __restrict__ x,
                                 const float* __restrict__ root,
                                 const float* __restrict__ bias)
{
    __shared__ float xr[IN_C];
    int n = blockIdx.x, t = threadIdx.x;
    if (t < IN_C) xr[t] = x[n * IN_C + t];
    __syncthreads();
    float v = __ldg(&bias[t]);
    #pragma unroll
    for (int i = 0; i < IN_C; i++)
        v = fmaf(xr[i], __ldg(&root[i * H64 + t]), v);
    g_agg[n * H64 + t] = v;
}

// ---------------- kernel 4: fused msg GEMM (mma.sync tf32) + scatter --------
// CTA = 128 edges x 64 outs, 8 warps; warp w owns rows [w*16, w*16+16).
// A[e, kap] = h[e, kap/IN] * x[src(e), kap%IN] synthesized in registers.
// B streamed via cp.async, triple-buffered, pair layout for LDS.64 b-frags.
template<int IN_C>
__global__ void __launch_bounds__(256)
fused_mma_kernel(const float* __restrict__ x, const int* __restrict__ ei, int E)
{
    constexpr int NCHUNK = (65 * IN_C) / 32;
    constexpr int XROW   = IN_C + 4;          // bank-spread: 36 or 68
    constexpr int B_OFF  = 0;                 // 3 x 8704
    constexpr int X_OFF  = 26112;
    constexpr int DST_OFF = X_OFF + 128 * XROW * 4;

    extern __shared__ char smem[];
    float* x_s   = (float*)(smem + X_OFF);
    int*   dst_s = (int*)(smem + DST_OFF);
    uint32_t sbase = smem_u32(smem);

    int tid = threadIdx.x;
    int e0  = blockIdx.x * 128;

    // ---- gather x[src] tile ----
    constexpr int XV = IN_C / 4;
    for (int q = tid; q < 128 * XV; q += 256) {
        int e = q / XV, cc = q % XV;
        int ge = e0 + e;
        int s = (ge < E) ? ei[ge] : 0;
        float4 v = *(const float4*)(x + (size_t)s * IN_C + cc * 4);
        *(float4*)&x_s[e * XROW + cc * 4] = v;
    }
    if (tid < 128) dst_s[tid] = (e0 + tid < E) ? ei[E + e0 + tid] : -1;

    // ---- B prefetch: 8704 B = 544 x 16B lines per chunk ----
    auto prefetch = [&](int c) {
        if (c < NCHUNK) {
            uint32_t bs = sbase + B_OFF + (c % 3) * 8704;
            const char* g = (const char*)g_w2b + (size_t)c * 8704;
            cp_async16(bs + tid * 16,        g + tid * 16);
            cp_async16(bs + 4096 + tid * 16, g + 4096 + tid * 16);
            if (tid < 32) cp_async16(bs + 8192 + tid * 16, g + 8192 + tid * 16);
        }
        CP_COMMIT();
    };
    prefetch(0);
    prefetch(1);
    __syncthreads();   // x_s visible to all warps

    const int w    = tid >> 5;
    const int lane = tid & 31;
    const int gid  = lane >> 2;
    const int tig  = lane & 3;
    const int r0   = w * 16 + gid;     // and r0+8

    float acc[8][4];
    #pragma unroll
    for (int q = 0; q < 8; q++)
        #pragma unroll
        for (int u = 0; u < 4; u++) acc[q][u] = 0.0f;

    const float* x0 = &x_s[r0 * XROW];
    const float* x1 = &x_s[(r0 + 8) * XROW];

    for (int c = 0; c < NCHUNK; c++) {
        CP_WAIT1();
        __syncthreads();      // chunk c resident everywhere; slot (c+2)%3 free
        prefetch(c + 2);

        int  kb  = c * 32;
        bool isB = (kb >= 64 * IN_C);
        int  i0  = kb % IN_C;
        float hv0 = 1.0f, hv1 = 1.0f;
        if (!isB) {
            const float* hp = &g_ht[(size_t)(kb / IN_C) * E + e0];
            hv0 = __ldg(hp + r0);
            hv1 = __ldg(hp + r0 + 8);
        }
        uint32_t bbase = sbase + B_OFF + (c % 3) * 8704;

        #pragma unroll
        for (int s = 0; s < 4; s++) {
            int i = i0 + s * 8 + tig;
            uint32_t a0 = tf32r(hv0 * x0[i]);
            uint32_t a1 = tf32r(hv1 * x1[i]);
            uint32_t a2 = tf32r(hv0 * x0[i + 4]);
            uint32_t a3 = tf32r(hv1 * x1[i + 4]);
            uint32_t brow = bbase + (uint32_t)(s * 4 + tig) * 544 + (uint32_t)gid * 8;
            #pragma unroll
            for (int q = 0; q < 8; q++) {
                uint32_t b0, b1;
                asm volatile("ld.shared.v2.b32 {%0, %1}, [%2];"
                             : "=r"(b0), "=r"(b1) : "r"(brow + q * 64));
                mma_tf32(acc[q], a0, a1, a2, a3, b0, b1);
            }
        }
    }

    // ---- scatter-add into agg[dst] ----
    int d0 = dst_s[r0], d1 = dst_s[r0 + 8];
    float* p0 = g_agg + (size_t)(d0 < 0 ? 0 : d0) * H64;
    float* p1 = g_agg + (size_t)(d1 < 0 ? 0 : d1) * H64;
    #pragma unroll
    for (int q = 0; q < 8; q++) {
        int n = q * 8 + tig * 2;
        if (d0 >= 0) {
            atomicAdd(p0 + n,     acc[q][0]);
            atomicAdd(p0 + n + 1, acc[q][1]);
        }
        if (d1 >= 0) {
            atomicAdd(p1 + n,     acc[q][2]);
            atomicAdd(p1 + n + 1, acc[q][3]);
        }
    }
}

// ---------------- kernel 5: out = relu(agg) ---------------------------------
__global__ void relu_out_kernel(float* __restrict__ out, int n)
{
    int i = blockIdx.x * blockDim.x + threadIdx.x;
    if (i < n) out[i] = fmaxf(g_agg[i], 0.0f);
}

// ---------------- launch -----------------------------------------------------
extern "C" void kernel_launch(void* const* d_in, const int* in_sizes, int n_in,
                              void* d_out, int out_size)
{
    const float* x      = (const float*)d_in[0];
    const int*   ei     = (const int*)  d_in[1];
    const float* ea     = (const float*)d_in[2];
    const float* w1_0   = (const float*)d_in[3];
    const float* b1_0   = (const float*)d_in[4];
    const float* w2_0   = (const float*)d_in[5];
    const float* b2_0   = (const float*)d_in[6];
    const float* root_0 = (const float*)d_in[7];
    const float* bias_0 = (const float*)d_in[8];
    const float* w1_1   = (const float*)d_in[9];
    const float* b1_1   = (const float*)d_in[10];
    const float* w2_1   = (const float*)d_in[11];
    const float* b2_1   = (const float*)d_in[12];
    const float* root_1 = (const float*)d_in[13];
    const float* bias_1 = (const float*)d_in[14];

    const int N = in_sizes[0] / 32;   // 20000
    const int E = in_sizes[1] / 2;    // 50000

    void* p = nullptr;
    cudaGetSymbolAddress(&p, g_x1);
    float* x1 = (float*)p;

    const int smem0 = 26112 + 128 * 36 * 4 + 512;   // 45056
    const int smem1 = 26112 + 128 * 68 * 4 + 512;   // 61440
    cudaFuncSetAttribute(fused_mma_kernel<32>,
                         cudaFuncAttributeMaxDynamicSharedMemorySize, smem0);
    cudaFuncSetAttribute(fused_mma_kernel<64>,
                         cudaFuncAttributeMaxDynamicSharedMemorySize, smem1);

    const int threads = 256;
    dim3 grid_h((E + threads - 1) / threads, H64);
    const int grid_fuse = (E + 127) / 128;
    const int grid_relu = (N * H64 + threads - 1) / threads;

    // ---------------- layer 0 (IN=32) ----------------
    edge_mlp_kernel<<<grid_h, threads>>>(ea, w1_0, b1_0, E);
    prep_w2b_kernel<32><<<(65 * 2048 + threads - 1) / threads, threads>>>(w2_0, b2_0);
    root_init_kernel<32><<<N, H64>>>(x, root_0, bias_0);
    fused_mma_kernel<32><<<grid_fuse, threads, smem0>>>(x, ei, E);
    relu_out_kernel<<<grid_relu, threads>>>(x1, N * H64);

    // ---------------- layer 1 (IN=64) ----------------
    edge_mlp_kernel<<<grid_h, threads>>>(ea, w1_1, b1_1, E);
    prep_w2b_kernel<64><<<(130 * 2048 + threads - 1) / threads, threads>>>(w2_1, b2_1);
    root_init_kernel<64><<<N, H64>>>(x1, root_1, bias_1);
    fused_mma_kernel<64><<<grid_fuse, threads, smem1>>>(x1, ei, E);
    relu_out_kernel<<<grid_relu, threads>>>((float*)d_out, N * H64);
}